// round 16
// baseline (speedup 1.0000x reference)
#include <cuda_runtime.h>

// MultiLayerGRU fused: 3 stacked GRU layers, T=1024, B=4096, I=5, H0=15, H1=10, H2=2.
// R12 base (704.5us): one warp per FOUR batches (two f32x2 packed pairs),
// duplicated (w,w) register weights, SMEM broadcast distribution, geometry
// 256 blocks x 128 thr, exact __fdividef/__expf epilogue.
// R16 change: INTRA-WARP PHASE SPLIT. The step body is two sequential
// half-bodies (one per batch pair), each with its own double-buffered u64
// broadcast buffer:
//   kloop(pair0) -> epilogue+publish(pair0) -> kloop(pair1) -> epilogue+
//   publish(pair1) -> syncwarp
// Pair1's 170-cyc FMA block is independent of pair0's epilogue, so the 12
// MUFU ops of epilogue0 overlap pair1's FMA issue instead of idling the fma
// pipe (R12 bunched all 24 MUFU of both warps into one end-of-step cluster).
// Buffers hold the packed 2-batch operand as u64: ld.shared.u64 IS the fma2
// operand (kills 50 pack MOVs/step); publish = 2 STS.64 per pair.
// Lane roles:
//   lanes  0..14 : layer-0 units     (read slots 27..51)
//   lanes 15..24 : layer-1 units     (read slots  0..24)
//   lanes 25..26 : layer-2 units     (read slots 15..39; store output)
//   lanes 27..31 : x loaders         (publish x; weights 0)
// Wavefront: step s computes h0(s), h1(s-1), h2(s-2).

#define T_STEPS 1024
#define BATCH   4096
#define IN_DIM  5

using u64 = unsigned long long;

__device__ __forceinline__ u64 pack2(float a, float b) {
    u64 r;
    asm("mov.b64 %0, {%1, %2};" : "=l"(r) : "f"(a), "f"(b));
    return r;
}
__device__ __forceinline__ void unpack2(u64 p, float& a, float& b) {
    asm("mov.b64 {%0, %1}, %2;" : "=f"(a), "=f"(b) : "l"(p));
}
__device__ __forceinline__ u64 fma2(u64 a, u64 b, u64 c) {
    u64 d;
    asm("fma.rn.f32x2 %0, %1, %2, %3;" : "=l"(d) : "l"(a), "l"(b), "l"(c));
    return d;
}

__device__ __forceinline__ float fsig(float a) {
    return __fdividef(1.0f, 1.0f + __expf(-a));
}
__device__ __forceinline__ float ftanh_(float v) {
    return 1.0f - 2.0f * __fdividef(1.0f, 1.0f + __expf(2.0f * v));
}

__global__ __launch_bounds__(128, 2)
void gru3_fused_kernel(
    const float* __restrict__ x,
    const float* __restrict__ w_ih0, const float* __restrict__ w_hh0,
    const float* __restrict__ b_ih0, const float* __restrict__ b_hh0,
    const float* __restrict__ w_ih1, const float* __restrict__ w_hh1,
    const float* __restrict__ b_ih1, const float* __restrict__ b_hh1,
    const float* __restrict__ w_ih2, const float* __restrict__ w_hh2,
    const float* __restrict__ b_ih2, const float* __restrict__ b_hh2,
    float* __restrict__ out)
{
    // ---- stage all weights into shared once ----
    __shared__ float sw[1884];
    // per-warp, per-pair, double-buffered u64 broadcast:
    // [warp][parity][pair][32 lanes + 32 wrap-dup]
    __shared__ __align__(16) u64 hbuf[4][2][2][64];
    {
        int t = threadIdx.x;
        for (int i = t; i < 225; i += 128) sw[i]        = w_ih0[i];
        for (int i = t; i < 675; i += 128) sw[225 + i]  = w_hh0[i];
        for (int i = t; i <  45; i += 128) sw[900 + i]  = b_ih0[i];
        for (int i = t; i <  45; i += 128) sw[945 + i]  = b_hh0[i];
        for (int i = t; i < 450; i += 128) sw[990 + i]  = w_ih1[i];
        for (int i = t; i < 300; i += 128) sw[1440 + i] = w_hh1[i];
        for (int i = t; i <  30; i += 128) sw[1740 + i] = b_ih1[i];
        for (int i = t; i <  30; i += 128) sw[1770 + i] = b_hh1[i];
        for (int i = t; i <  60; i += 128) sw[1800 + i] = w_ih2[i];
        for (int i = t; i <  12; i += 128) sw[1860 + i] = w_hh2[i];
        for (int i = t; i <   6; i += 128) sw[1872 + i] = b_ih2[i];
        for (int i = t; i <   6; i += 128) sw[1878 + i] = b_hh2[i];
    }
    __syncthreads();
    const float* s_wih0 = sw;
    const float* s_whh0 = sw + 225;
    const float* s_bih0 = sw + 900;
    const float* s_bhh0 = sw + 945;
    const float* s_wih1 = sw + 990;
    const float* s_whh1 = sw + 1440;
    const float* s_bih1 = sw + 1740;
    const float* s_bhh1 = sw + 1770;
    const float* s_wih2 = sw + 1800;
    const float* s_whh2 = sw + 1860;
    const float* s_bih2 = sw + 1872;
    const float* s_bhh2 = sw + 1878;

    const int lane = threadIdx.x & 31;
    const int wid  = threadIdx.x >> 5;
    const int gw   = blockIdx.x * 4 + wid;
    const int b0   = gw * 4;           // batches b0 .. b0+3

    // ---- per-lane register-resident weights (unified k-loop, k = 0..24) ----
    float wr[25], wz[25], wni[15], wnh[20];
#pragma unroll
    for (int k = 0; k < 25; k++) { wr[k] = 0.f; wz[k] = 0.f; }
#pragma unroll
    for (int k = 0; k < 15; k++) wni[k] = 0.f;
#pragma unroll
    for (int k = 0; k < 20; k++) wnh[k] = 0.f;
    float br = 0.f, bz = 0.f, bni = 0.f, bnh = 0.f;

    if (lane < 15) {
        const int u = lane;
#pragma unroll
        for (int k = 0; k < 5; k++) {
            wr[k]  = s_wih0[u * 5 + k];
            wz[k]  = s_wih0[(15 + u) * 5 + k];
            wni[k] = s_wih0[(30 + u) * 5 + k];
        }
#pragma unroll
        for (int j = 0; j < 15; j++) {
            wr[5 + j]  = s_whh0[u * 15 + j];
            wz[5 + j]  = s_whh0[(15 + u) * 15 + j];
            wnh[j]     = s_whh0[(30 + u) * 15 + j];
        }
        br  = s_bih0[u] + s_bhh0[u];
        bz  = s_bih0[15 + u] + s_bhh0[15 + u];
        bni = s_bih0[30 + u];
        bnh = s_bhh0[30 + u];
    } else if (lane < 25) {
        const int u = lane - 15;
#pragma unroll
        for (int k = 0; k < 15; k++) {
            wr[k]  = s_wih1[u * 15 + k];
            wz[k]  = s_wih1[(10 + u) * 15 + k];
            wni[k] = s_wih1[(20 + u) * 15 + k];
        }
#pragma unroll
        for (int j = 0; j < 10; j++) {
            wr[15 + j]  = s_whh1[u * 10 + j];
            wz[15 + j]  = s_whh1[(10 + u) * 10 + j];
            wnh[10 + j] = s_whh1[(20 + u) * 10 + j];
        }
        br  = s_bih1[u] + s_bhh1[u];
        bz  = s_bih1[10 + u] + s_bhh1[10 + u];
        bni = s_bih1[20 + u];
        bnh = s_bhh1[20 + u];
    } else if (lane < 27) {
        const int u = lane - 25;
#pragma unroll
        for (int k = 0; k < 10; k++) {
            wr[k]  = s_wih2[u * 10 + k];
            wz[k]  = s_wih2[(2 + u) * 10 + k];
            wni[k] = s_wih2[(4 + u) * 10 + k];
        }
#pragma unroll
        for (int j = 0; j < 2; j++) {
            wr[10 + j] = s_whh2[u * 2 + j];
            wz[10 + j] = s_whh2[(2 + u) * 2 + j];
            wnh[5 + j] = s_whh2[(4 + u) * 2 + j];
        }
        br  = s_bih2[u] + s_bhh2[u];
        bz  = s_bih2[2 + u] + s_bhh2[2 + u];
        bni = s_bih2[4 + u];
        bnh = s_bhh2[4 + u];
    }

    // duplicate-packed weights (w,w) for f32x2 FMA — shared by both pairs
    u64 wr2[25], wz2[25], wni2[15], wnh2[20];
#pragma unroll
    for (int k = 0; k < 25; k++) { wr2[k] = pack2(wr[k], wr[k]); wz2[k] = pack2(wz[k], wz[k]); }
#pragma unroll
    for (int k = 0; k < 15; k++) wni2[k] = pack2(wni[k], wni[k]);
#pragma unroll
    for (int k = 0; k < 20; k++) wnh2[k] = pack2(wnh[k], wnh[k]);
    const u64 br2  = pack2(br, br);
    const u64 bz2  = pack2(bz, bz);
    const u64 bni2 = pack2(bni, bni);
    const u64 bnh2 = pack2(bnh, bnh);

    // read base per lane class (wrap handled by duplicate store at lane+32)
    const int base = (lane < 15) ? 27 : (lane < 25) ? 0 : (lane < 27) ? 15 : 0;

    // wavefront delay per lane; loader lanes never commit
    const int d = (lane < 15) ? 0 : (lane < 25) ? 1 : (lane < 27) ? 2 : 0x40000000;
    const bool isOut = (lane == 25) || (lane == 26);

    const int feat = (lane >= 27) ? (lane - 27) : 0;
    const float* xp = x + (size_t)b0 * IN_DIM + feat;
    const int u2 = (lane >= 25) ? (lane - 25) : 0;
    float* op = out + (size_t)b0 * 2 + u2;

    float h[4] = {0.f, 0.f, 0.f, 0.f};   // hidden state, 4 batches
    float xn[4] = {0.f, 0.f, 0.f, 0.f};  // prefetched x(t+1)
    u64 sh0 = 0, sh1 = 0;                // packed operands (b0,b1) / (b2,b3)
    if (lane >= 27) {
        sh0 = pack2(xp[0 * IN_DIM], xp[1 * IN_DIM]);             // x(0)
        sh1 = pack2(xp[2 * IN_DIM], xp[3 * IN_DIM]);
#pragma unroll
        for (int j = 0; j < 4; j++) xn[j] = xp[BATCH * IN_DIM + j * IN_DIM];  // x(1)
    }

    const u64* rdA0 = &hbuf[wid][0][0][base];
    const u64* rdB0 = &hbuf[wid][0][1][base];
    const u64* rdA1 = &hbuf[wid][1][0][base];
    const u64* rdB1 = &hbuf[wid][1][1][base];
    u64* wpA0 = &hbuf[wid][0][0][lane];
    u64* wpB0 = &hbuf[wid][0][1][lane];
    u64* wpA1 = &hbuf[wid][1][0][lane];
    u64* wpB1 = &hbuf[wid][1][1][lane];

    // initial publish of (x(0), h=0) into parity 0
    wpA0[0] = sh0; wpA0[32] = sh0;
    wpB0[0] = sh1; wpB0[32] = sh1;
    __syncwarp(0xffffffffu);

    // one half-body: k-loop + epilogue + publish for ONE batch pair.
    // hj0/hj1 index this pair's two batches (0,1 or 2,3).
    auto half = [&](int s, const u64* rd, u64* wp, int hj0, int hj1,
                    u64& shp, bool isPair1) {
        u64 ar = br2, az = bz2, ani = bni2, anh = bnh2;
#pragma unroll
        for (int k = 0; k < 25; k++) {
            u64 v = rd[k];                       // ld.shared.u64, imm offset
            ar = fma2(wr2[k], v, ar);
            az = fma2(wz2[k], v, az);
            if (k < 15) ani = fma2(wni2[k], v, ani);
            if (k >= 5) anh = fma2(wnh2[k - 5], v, anh);
        }

        float arA, arB, azA, azB, aniA, aniB, anhA, anhB;
        unpack2(ar, arA, arB);
        unpack2(az, azA, azB);
        unpack2(ani, aniA, aniB);
        unpack2(anh, anhA, anhB);

        float rA = fsig(arA), rB = fsig(arB);
        float zA = fsig(azA), zB = fsig(azB);
        float nA = ftanh_(fmaf(rA, anhA, aniA));
        float nB = ftanh_(fmaf(rB, anhB, aniB));
        float hnA = fmaf(zA, h[hj0] - nA, nA);   // (1-z)*n + z*h
        float hnB = fmaf(zB, h[hj1] - nB, nB);

        bool valid = (s >= d) && (s < T_STEPS + d);
        if (valid) { h[hj0] = hnA; h[hj1] = hnB; }
        if (valid && isOut) {
            size_t o = (size_t)(s - 2) * (BATCH * 2);
            op[o + hj0 * 2] = hnA;
            op[o + hj1 * 2] = hnB;
        }

        if (lane < 27) {
            shp = pack2(h[hj0], h[hj1]);
        } else {
            shp = pack2(xn[hj0], xn[hj1]);       // becomes x(s+1)
            if (isPair1) {                       // advance prefetch once/step
                int t2 = s + 2;
                bool inb = (t2 < T_STEPS);
                size_t xo = (size_t)t2 * (BATCH * IN_DIM);
#pragma unroll
                for (int j = 0; j < 4; j++) xn[j] = inb ? xp[xo + j * IN_DIM] : 0.f;
            }
        }
        wp[0] = shp; wp[32] = shp;               // 2x STS.64
    };

    auto body = [&](int s, const u64* rdA, const u64* rdB, u64* wpA, u64* wpB) {
        half(s, rdA, wpA, 0, 1, sh0, false);     // pair0: kloop+epi+publish
        half(s, rdB, wpB, 2, 3, sh1, true);      // pair1 FMA overlaps epi0
        __syncwarp(0xffffffffu);
    };

    // 1026 steps, manual 2x unroll for compile-time buffer parity
    for (int s = 0; s < T_STEPS + 2; s += 2) {
        body(s,     rdA0, rdB0, wpA1, wpB1);
        body(s + 1, rdA1, rdB1, wpA0, wpB0);
    }
}

extern "C" void kernel_launch(void* const* d_in, const int* in_sizes, int n_in,
                              void* d_out, int out_size)
{
    (void)in_sizes; (void)n_in; (void)out_size;
    const float* x     = (const float*)d_in[0];
    const float* w_ih0 = (const float*)d_in[1];
    const float* w_hh0 = (const float*)d_in[2];
    const float* b_ih0 = (const float*)d_in[3];
    const float* b_hh0 = (const float*)d_in[4];
    const float* w_ih1 = (const float*)d_in[5];
    const float* w_hh1 = (const float*)d_in[6];
    const float* b_ih1 = (const float*)d_in[7];
    const float* b_hh1 = (const float*)d_in[8];
    const float* w_ih2 = (const float*)d_in[9];
    const float* w_hh2 = (const float*)d_in[10];
    const float* b_ih2 = (const float*)d_in[11];
    const float* b_hh2 = (const float*)d_in[12];

    // one warp per 4 batch elements: 1024 warps = 256 blocks x 4 warps
    gru3_fused_kernel<<<BATCH / 16, 128>>>(
        x, w_ih0, w_hh0, b_ih0, b_hh0,
        w_ih1, w_hh1, b_ih1, b_hh1,
        w_ih2, w_hh2, b_ih2, b_hh2,
        (float*)d_out);
}

// round 17
// speedup vs baseline: 1.2215x; 1.2215x over previous
#include <cuda_runtime.h>

// MultiLayerGRU fused: 3 stacked GRU layers, T=1024, B=4096, I=5, H0=15, H1=10, H2=2.
// R12 core (704.5us, best): one warp per FOUR batches (two f32x2 packed
// pairs), duplicated (w,w) register weights, per-warp double-buffered SMEM
// float4 broadcast (25 LDS.128 + 2 STS.128 + 1 syncwarp per step), geometry
// 256 blocks x 128 thr (4 warps, proper SMSP spread), exact exp/rcp epilogue.
// R17 change: LOOP PEEL (R5's package, first fair test on sane geometry).
//   prologue s=0,1: gated h-commit, no store.
//   steady  s=2..1021: UNCONDITIONAL commit + store (post-T upstream commits
//     are never consumed; loader-lane h never used; store range t=0..1023).
//   tail    s=1022..1025: unconditional commit + store, no x prefetch.
// Removes the per-step valid compare/select chain, the t2<T select, and the
// per-store offset IMAD (output pointer bumped by constant).
// Lane roles:
//   lanes  0..14 : layer-0 units     (read slots 27..51)
//   lanes 15..24 : layer-1 units     (read slots  0..24)
//   lanes 25..26 : layer-2 units     (read slots 15..39; store output)
//   lanes 27..31 : x loaders         (publish x; weights 0)
// Wavefront: step s computes h0(s), h1(s-1), h2(s-2).

#define T_STEPS 1024
#define BATCH   4096
#define IN_DIM  5

using u64 = unsigned long long;

__device__ __forceinline__ u64 pack2(float a, float b) {
    u64 r;
    asm("mov.b64 %0, {%1, %2};" : "=l"(r) : "f"(a), "f"(b));
    return r;
}
__device__ __forceinline__ void unpack2(u64 p, float& a, float& b) {
    asm("mov.b64 {%0, %1}, %2;" : "=f"(a), "=f"(b) : "l"(p));
}
__device__ __forceinline__ u64 fma2(u64 a, u64 b, u64 c) {
    u64 d;
    asm("fma.rn.f32x2 %0, %1, %2, %3;" : "=l"(d) : "l"(a), "l"(b), "l"(c));
    return d;
}

__device__ __forceinline__ float fsig(float a) {
    return __fdividef(1.0f, 1.0f + __expf(-a));
}
__device__ __forceinline__ float ftanh_(float v) {
    return 1.0f - 2.0f * __fdividef(1.0f, 1.0f + __expf(2.0f * v));
}

__global__ __launch_bounds__(128, 2)
void gru3_fused_kernel(
    const float* __restrict__ x,
    const float* __restrict__ w_ih0, const float* __restrict__ w_hh0,
    const float* __restrict__ b_ih0, const float* __restrict__ b_hh0,
    const float* __restrict__ w_ih1, const float* __restrict__ w_hh1,
    const float* __restrict__ b_ih1, const float* __restrict__ b_hh1,
    const float* __restrict__ w_ih2, const float* __restrict__ w_hh2,
    const float* __restrict__ b_ih2, const float* __restrict__ b_hh2,
    float* __restrict__ out)
{
    // ---- stage all weights into shared once ----
    __shared__ float sw[1884];
    // per-warp double-buffered broadcast: [warp][parity][32 lanes + 32 dup]
    __shared__ __align__(16) float4 hbuf[4][2][64];
    {
        int t = threadIdx.x;
        for (int i = t; i < 225; i += 128) sw[i]        = w_ih0[i];
        for (int i = t; i < 675; i += 128) sw[225 + i]  = w_hh0[i];
        for (int i = t; i <  45; i += 128) sw[900 + i]  = b_ih0[i];
        for (int i = t; i <  45; i += 128) sw[945 + i]  = b_hh0[i];
        for (int i = t; i < 450; i += 128) sw[990 + i]  = w_ih1[i];
        for (int i = t; i < 300; i += 128) sw[1440 + i] = w_hh1[i];
        for (int i = t; i <  30; i += 128) sw[1740 + i] = b_ih1[i];
        for (int i = t; i <  30; i += 128) sw[1770 + i] = b_hh1[i];
        for (int i = t; i <  60; i += 128) sw[1800 + i] = w_ih2[i];
        for (int i = t; i <  12; i += 128) sw[1860 + i] = w_hh2[i];
        for (int i = t; i <   6; i += 128) sw[1872 + i] = b_ih2[i];
        for (int i = t; i <   6; i += 128) sw[1878 + i] = b_hh2[i];
    }
    __syncthreads();
    const float* s_wih0 = sw;
    const float* s_whh0 = sw + 225;
    const float* s_bih0 = sw + 900;
    const float* s_bhh0 = sw + 945;
    const float* s_wih1 = sw + 990;
    const float* s_whh1 = sw + 1440;
    const float* s_bih1 = sw + 1740;
    const float* s_bhh1 = sw + 1770;
    const float* s_wih2 = sw + 1800;
    const float* s_whh2 = sw + 1860;
    const float* s_bih2 = sw + 1872;
    const float* s_bhh2 = sw + 1878;

    const int lane = threadIdx.x & 31;
    const int wid  = threadIdx.x >> 5;
    const int gw   = blockIdx.x * 4 + wid;
    const int b0   = gw * 4;           // batches b0 .. b0+3

    // ---- per-lane register-resident weights (unified k-loop, k = 0..24) ----
    float wr[25], wz[25], wni[15], wnh[20];
#pragma unroll
    for (int k = 0; k < 25; k++) { wr[k] = 0.f; wz[k] = 0.f; }
#pragma unroll
    for (int k = 0; k < 15; k++) wni[k] = 0.f;
#pragma unroll
    for (int k = 0; k < 20; k++) wnh[k] = 0.f;
    float br = 0.f, bz = 0.f, bni = 0.f, bnh = 0.f;

    if (lane < 15) {
        const int u = lane;
#pragma unroll
        for (int k = 0; k < 5; k++) {
            wr[k]  = s_wih0[u * 5 + k];
            wz[k]  = s_wih0[(15 + u) * 5 + k];
            wni[k] = s_wih0[(30 + u) * 5 + k];
        }
#pragma unroll
        for (int j = 0; j < 15; j++) {
            wr[5 + j]  = s_whh0[u * 15 + j];
            wz[5 + j]  = s_whh0[(15 + u) * 15 + j];
            wnh[j]     = s_whh0[(30 + u) * 15 + j];
        }
        br  = s_bih0[u] + s_bhh0[u];
        bz  = s_bih0[15 + u] + s_bhh0[15 + u];
        bni = s_bih0[30 + u];
        bnh = s_bhh0[30 + u];
    } else if (lane < 25) {
        const int u = lane - 15;
#pragma unroll
        for (int k = 0; k < 15; k++) {
            wr[k]  = s_wih1[u * 15 + k];
            wz[k]  = s_wih1[(10 + u) * 15 + k];
            wni[k] = s_wih1[(20 + u) * 15 + k];
        }
#pragma unroll
        for (int j = 0; j < 10; j++) {
            wr[15 + j]  = s_whh1[u * 10 + j];
            wz[15 + j]  = s_whh1[(10 + u) * 10 + j];
            wnh[10 + j] = s_whh1[(20 + u) * 10 + j];
        }
        br  = s_bih1[u] + s_bhh1[u];
        bz  = s_bih1[10 + u] + s_bhh1[10 + u];
        bni = s_bih1[20 + u];
        bnh = s_bhh1[20 + u];
    } else if (lane < 27) {
        const int u = lane - 25;
#pragma unroll
        for (int k = 0; k < 10; k++) {
            wr[k]  = s_wih2[u * 10 + k];
            wz[k]  = s_wih2[(2 + u) * 10 + k];
            wni[k] = s_wih2[(4 + u) * 10 + k];
        }
#pragma unroll
        for (int j = 0; j < 2; j++) {
            wr[10 + j] = s_whh2[u * 2 + j];
            wz[10 + j] = s_whh2[(2 + u) * 2 + j];
            wnh[5 + j] = s_whh2[(4 + u) * 2 + j];
        }
        br  = s_bih2[u] + s_bhh2[u];
        bz  = s_bih2[2 + u] + s_bhh2[2 + u];
        bni = s_bih2[4 + u];
        bnh = s_bhh2[4 + u];
    }

    // duplicate-packed weights (w,w) for f32x2 FMA — shared by both batch pairs
    u64 wr2[25], wz2[25], wni2[15], wnh2[20];
#pragma unroll
    for (int k = 0; k < 25; k++) { wr2[k] = pack2(wr[k], wr[k]); wz2[k] = pack2(wz[k], wz[k]); }
#pragma unroll
    for (int k = 0; k < 15; k++) wni2[k] = pack2(wni[k], wni[k]);
#pragma unroll
    for (int k = 0; k < 20; k++) wnh2[k] = pack2(wnh[k], wnh[k]);
    const u64 br2  = pack2(br, br);
    const u64 bz2  = pack2(bz, bz);
    const u64 bni2 = pack2(bni, bni);
    const u64 bnh2 = pack2(bnh, bnh);

    // read base per lane class (wrap handled by duplicate store at lane+32)
    const int base = (lane < 15) ? 27 : (lane < 25) ? 0 : (lane < 27) ? 15 : 0;

    // wavefront delay per lane (prologue commit gate only)
    const int d = (lane < 15) ? 0 : (lane < 25) ? 1 : (lane < 27) ? 2 : 0x40000000;
    const bool isOut = (lane == 25) || (lane == 26);
    const bool isLoader = (lane >= 27);

    const int feat = isLoader ? (lane - 27) : 0;
    const float* xp = x + (size_t)b0 * IN_DIM + feat;
    const int u2 = (lane >= 25) ? (lane - 25) : 0;
    float* op = out + (size_t)b0 * 2 + u2;      // bumped by BATCH*2 per step

    float h[4] = {0.f, 0.f, 0.f, 0.f};   // hidden state, 4 batches
    float xn[4] = {0.f, 0.f, 0.f, 0.f};  // prefetched x(t+1)
    u64 sh0 = 0, sh1 = 0;                // packed operands (b0,b1) / (b2,b3)
    size_t xoff = 2 * (size_t)(BATCH * IN_DIM);   // offset of x(2), loaded at s=0
    if (isLoader) {
        sh0 = pack2(xp[0 * IN_DIM], xp[1 * IN_DIM]);             // x(0)
        sh1 = pack2(xp[2 * IN_DIM], xp[3 * IN_DIM]);
#pragma unroll
        for (int j = 0; j < 4; j++) xn[j] = xp[BATCH * IN_DIM + j * IN_DIM];  // x(1)
    }

    const float4* rd0 = &hbuf[wid][0][base];
    const float4* rd1 = &hbuf[wid][1][base];
    float4* wp0 = &hbuf[wid][0][lane];
    float4* wp1 = &hbuf[wid][1][lane];

    // initial publish of (x(0), h=0) into parity 0
    {
        float s0a, s0b, s1a, s1b;
        unpack2(sh0, s0a, s0b);
        unpack2(sh1, s1a, s1b);
        float4 v = make_float4(s0a, s0b, s1a, s1b);
        wp0[0] = v; wp0[32] = v;
    }
    __syncwarp(0xffffffffu);

    // Core step. prologue: gated commit, no store. steady/tail: unconditional
    // commit + store. loadX: x(t+2) prefetch in-bounds (steady) or zero (tail).
    auto body = [&](int s, const float4* rd, float4* wp, bool prologue, bool loadX) {
        u64 ar0 = br2, az0 = bz2, ani0 = bni2, anh0 = bnh2;
        u64 ar1 = br2, az1 = bz2, ani1 = bni2, anh1 = bnh2;
#pragma unroll
        for (int k = 0; k < 25; k++) {
            float4 q = rd[k];                 // ld.shared.v4, immediate offset
            u64 v0 = pack2(q.x, q.y);
            u64 v1 = pack2(q.z, q.w);
            ar0 = fma2(wr2[k], v0, ar0);
            ar1 = fma2(wr2[k], v1, ar1);
            az0 = fma2(wz2[k], v0, az0);
            az1 = fma2(wz2[k], v1, az1);
            if (k < 15) { ani0 = fma2(wni2[k], v0, ani0); ani1 = fma2(wni2[k], v1, ani1); }
            if (k >= 5) { anh0 = fma2(wnh2[k - 5], v0, anh0); anh1 = fma2(wnh2[k - 5], v1, anh1); }
        }

        float arf[4], azf[4], anif[4], anhf[4], hn[4];
        unpack2(ar0, arf[0], arf[1]);    unpack2(ar1, arf[2], arf[3]);
        unpack2(az0, azf[0], azf[1]);    unpack2(az1, azf[2], azf[3]);
        unpack2(ani0, anif[0], anif[1]); unpack2(ani1, anif[2], anif[3]);
        unpack2(anh0, anhf[0], anhf[1]); unpack2(anh1, anhf[2], anhf[3]);
#pragma unroll
        for (int j = 0; j < 4; j++) {
            float r = fsig(arf[j]);
            float z = fsig(azf[j]);
            float n = ftanh_(fmaf(r, anhf[j], anif[j]));
            hn[j] = fmaf(z, h[j] - n, n);                        // (1-z)*n + z*h
        }

        if (prologue) {
            if (d <= s) {
#pragma unroll
                for (int j = 0; j < 4; j++) h[j] = hn[j];
            }
        } else {
            // steady/tail: unconditional commit (upstream post-T values never
            // consumed; loader h never used) + unconditional store (t=s-2)
#pragma unroll
            for (int j = 0; j < 4; j++) h[j] = hn[j];
            if (isOut) {
#pragma unroll
                for (int j = 0; j < 4; j++) op[j * 2] = hn[j];
            }
            op += BATCH * 2;
        }

        if (isLoader) {
            sh0 = pack2(xn[0], xn[1]);                           // becomes x(s+1)
            sh1 = pack2(xn[2], xn[3]);
            if (loadX) {
#pragma unroll
                for (int j = 0; j < 4; j++) xn[j] = xp[xoff + j * IN_DIM];
            } else {
#pragma unroll
                for (int j = 0; j < 4; j++) xn[j] = 0.f;
            }
            xoff += BATCH * IN_DIM;
        } else {
            sh0 = pack2(h[0], h[1]);
            sh1 = pack2(h[2], h[3]);
        }

        float s0a, s0b, s1a, s1b;
        unpack2(sh0, s0a, s0b);
        unpack2(sh1, s1a, s1b);
        float4 v = make_float4(s0a, s0b, s1a, s1b);
        wp[0] = v; wp[32] = v;
        __syncwarp(0xffffffffu);
    };

    // prologue: s=0 (L0 commits), s=1 (L0,L1 commit); no stores
    body(0, rd0, wp1, true, true);
    body(1, rd1, wp0, true, true);
    // steady: s=2..1021 (1020 steps, 510 parity pairs); x(t+2) in-bounds
    for (int s = 2; s <= 1021; s += 2) {
        body(s,     rd0, wp1, false, true);
        body(s + 1, rd1, wp0, false, true);
    }
    // tail: s=1022..1025; x prefetch out of bounds -> zeros
    body(1022, rd0, wp1, false, false);
    body(1023, rd1, wp0, false, false);
    body(1024, rd0, wp1, false, false);
    body(1025, rd1, wp0, false, false);
}

extern "C" void kernel_launch(void* const* d_in, const int* in_sizes, int n_in,
                              void* d_out, int out_size)
{
    (void)in_sizes; (void)n_in; (void)out_size;
    const float* x     = (const float*)d_in[0];
    const float* w_ih0 = (const float*)d_in[1];
    const float* w_hh0 = (const float*)d_in[2];
    const float* b_ih0 = (const float*)d_in[3];
    const float* b_hh0 = (const float*)d_in[4];
    const float* w_ih1 = (const float*)d_in[5];
    const float* w_hh1 = (const float*)d_in[6];
    const float* b_ih1 = (const float*)d_in[7];
    const float* b_hh1 = (const float*)d_in[8];
    const float* w_ih2 = (const float*)d_in[9];
    const float* w_hh2 = (const float*)d_in[10];
    const float* b_ih2 = (const float*)d_in[11];
    const float* b_hh2 = (const float*)d_in[12];

    // one warp per 4 batch elements: 1024 warps = 256 blocks x 4 warps
    gru3_fused_kernel<<<BATCH / 16, 128>>>(
        x, w_ih0, w_hh0, b_ih0, b_hh0,
        w_ih1, w_hh1, b_ih1, b_hh1,
        w_ih2, w_hh2, b_ih2, b_hh2,
        (float*)d_out);
}